// round 13
// baseline (speedup 1.0000x reference)
#include <cuda_runtime.h>
#include <cuda_fp16.h>
#include <cstdint>

// DSAttention flash attention: QK in tf32 mma.m16n8k8, PV in fp16 mma.m16n8k16
// with the S->A fragment identity (P never touches smem). Full double-buffered
// cp.async (K, V, delta), ONE barrier per tile, 4 CTAs/SM.
// Prep kernel: K rna->tf32 interleaved (c,c+4); V -> fp16 transposed [e][s]
// with 16-group interleave {2t4,2t4+1,2t4+8,2t4+9} -> one LDS.64 per B-frag.

#define LQ 2048
#define HH 8
#define BM 64
#define BN 64
#define ED 64
#define NTHREADS 128
#define KSTR 72            // floats; 72%32==8 -> 2-way max on frag LDS.64
#define VSH 72             // halves per e-row (144 B)

#define SK_F   (64 * KSTR)             // 4608 floats per K buffer
#define SVH_B  (64 * VSH * 2)          // 9216 bytes per V buffer
// float-indexed layout
#define OFF_K0 0
#define OFF_K1 (SK_F)
#define OFF_VH (2 * SK_F)              // 2 half-buffers = 4608 floats
#define OFF_D  (OFF_VH + (2 * SVH_B) / 4)
#define SMEM_FLOATS (OFF_D + 128 + 16)
#define SMEM_BYTES  (SMEM_FLOATS * 4)  // ~55.9 KB -> 4 CTAs/SM

__device__ float  g_Kp[2 * 8 * 2048 * 64];    // 8 MB: tf32-rounded, interleaved
__device__ __half g_Vth[2 * 8 * 64 * 2048];   // 4 MB: fp16, [bh][e][s] interleaved

__device__ __forceinline__ float tf32r(float x) {
    uint32_t u;
    asm("cvt.rna.tf32.f32 %0, %1;" : "=r"(u) : "f"(x));
    return __uint_as_float(u);
}
__device__ __forceinline__ uint32_t pack_h2(float a, float b) {
    __half2 h = __floats2half2_rn(a, b);   // lo=a, hi=b
    return *(uint32_t*)&h;
}
__device__ __forceinline__ void cpasync16(uint32_t dst, const void* src) {
    asm volatile("cp.async.cg.shared.global [%0], [%1], 16;" :: "r"(dst), "l"(src));
}
__device__ __forceinline__ void cp_commit() {
    asm volatile("cp.async.commit_group;" ::: "memory");
}
__device__ __forceinline__ void cp_wait0() {
    asm volatile("cp.async.wait_group 0;" ::: "memory");
}

__device__ __forceinline__ void mma_tf32(float* d, const uint32_t* a,
                                         uint32_t b0, uint32_t b1) {
    asm volatile(
        "mma.sync.aligned.m16n8k8.row.col.f32.tf32.tf32.f32 "
        "{%0,%1,%2,%3}, {%4,%5,%6,%7}, {%8,%9}, {%0,%1,%2,%3};"
        : "+f"(d[0]), "+f"(d[1]), "+f"(d[2]), "+f"(d[3])
        : "r"(a[0]), "r"(a[1]), "r"(a[2]), "r"(a[3]), "r"(b0), "r"(b1));
}
__device__ __forceinline__ void mma_f16(float* d, const uint32_t* a,
                                        uint32_t b0, uint32_t b1) {
    asm volatile(
        "mma.sync.aligned.m16n8k16.row.col.f32.f16.f16.f32 "
        "{%0,%1,%2,%3}, {%4,%5,%6,%7}, {%8,%9}, {%0,%1,%2,%3};"
        : "+f"(d[0]), "+f"(d[1]), "+f"(d[2]), "+f"(d[3])
        : "r"(a[0]), "r"(a[1]), "r"(a[2]), "r"(a[3]), "r"(b0), "r"(b1));
}

// ---------------- prep ----------------
__global__ __launch_bounds__(256)
void prep_kernel(const float* __restrict__ Kg, const float* __restrict__ Vg)
{
    const int stile = blockIdx.x;
    const int h     = blockIdx.y;
    const int b     = blockIdx.z;
    const int tid   = threadIdx.x;
    const int bh    = b * HH + h;
    const int s0    = stile * 64;

    __shared__ float tile[64][65];

    // K: rna-round + (c, c+4) interleave per 8-group; [bh][s][64]
    const float* Kbh = Kg + ((size_t)(b * LQ) * HH + h) * ED;
    float* Kp = g_Kp + (size_t)bh * LQ * ED;
    #pragma unroll
    for (int it = 0; it < 2; ++it) {
        int u  = tid + it * 256;
        int r  = u >> 3;
        int c8 = u & 7;
        const float* src = Kbh + (size_t)(s0 + r) * (HH * ED) + 8 * c8;
        float4 a  = *(const float4*)(src);
        float4 bb = *(const float4*)(src + 4);
        a.x = tf32r(a.x); a.y = tf32r(a.y); a.z = tf32r(a.z); a.w = tf32r(a.w);
        bb.x = tf32r(bb.x); bb.y = tf32r(bb.y); bb.z = tf32r(bb.z); bb.w = tf32r(bb.w);
        float* dst = Kp + (size_t)(s0 + r) * ED + 8 * c8;
        *(float4*)(dst)     = make_float4(a.x, bb.x, a.y, bb.y);
        *(float4*)(dst + 4) = make_float4(a.z, bb.z, a.w, bb.w);
    }

    // V: fp16, transpose to [bh][e][2048], 16-group interleave
    const float* Vbh = Vg + ((size_t)(b * LQ) * HH + h) * ED;
    #pragma unroll
    for (int it = 0; it < 4; ++it) {
        int u  = tid + it * 256;
        int r  = u >> 4;
        int c4 = u & 15;
        float4 v = *(const float4*)(Vbh + (size_t)(s0 + r) * (HH * ED) + 4 * c4);
        tile[r][4 * c4 + 0] = v.x;
        tile[r][4 * c4 + 1] = v.y;
        tile[r][4 * c4 + 2] = v.z;
        tile[r][4 * c4 + 3] = v.w;
    }
    __syncthreads();
    // 256 units: e (64) x 16-group (4). Physical p holds logical
    // s = 2*(p>>2) + (p&1) + 8*((p>>1)&1)  within the 16-group.
    {
        int e   = tid >> 2;
        int grp = tid & 3;
        __half hh16[16];
        #pragma unroll
        for (int p = 0; p < 16; ++p) {
            int s_l = grp * 16 + 2 * (p >> 2) + (p & 1) + 8 * ((p >> 1) & 1);
            hh16[p] = __float2half_rn(tile[s_l][e]);
        }
        __half* dst = g_Vth + ((size_t)bh * ED + e) * LQ + s0 + grp * 16;
        *(uint4*)(dst)     = *(uint4*)(hh16);
        *(uint4*)(dst + 8) = *(uint4*)(hh16 + 8);
    }
}

// ---------------- main ----------------
__global__ __launch_bounds__(NTHREADS, 4)
void dsattn_tc(const float* __restrict__ Qg, const float* __restrict__ Taug,
               const float* __restrict__ Dg, float* __restrict__ Og)
{
    const float scale = 0.125f;

    const int mtile = (int)gridDim.x - 1 - (int)blockIdx.x;
    const int h     = blockIdx.y;
    const int b     = blockIdx.z;
    const int bh    = b * HH + h;

    const int tid  = threadIdx.x;
    const int wid  = tid >> 5;
    const int lane = tid & 31;
    const int g    = lane >> 2;
    const int t4   = lane & 3;

    extern __shared__ float smem[];
    float*  sK[2];
    sK[0] = smem + OFF_K0;
    sK[1] = smem + OFF_K1;
    __half* sVh[2];
    sVh[0] = (__half*)(smem + OFF_VH);
    sVh[1] = sVh[0] + 64 * VSH;
    float* sD[2];
    sD[0] = smem + OFF_D;
    sD[1] = sD[0] + 64;

    const uint32_t su   = (uint32_t)__cvta_generic_to_shared(smem);
    const uint32_t sKu[2]  = { su + OFF_K0 * 4, su + OFF_K1 * 4 };
    const uint32_t sVhu[2] = { su + OFF_VH * 4, su + OFF_VH * 4 + SVH_B };
    const uint32_t sDu[2]  = { su + OFF_D * 4,  su + OFF_D * 4 + 256 };

    const float ts = Taug[b] * scale;
    const int wrow = wid * 16;

    const float*  Qbase  = Qg + ((size_t)(b * LQ) * HH + h) * ED;
    const float*  Kpbase = g_Kp + (size_t)bh * LQ * ED;
    const __half* Vtbase = g_Vth + (size_t)bh * ED * LQ;
    const float*  Dbase  = Dg + b * LQ;

    const int nkt = mtile + 1;

    // ---- prologue: Q -> sK1 (staging), K0, V0, D0 ----
    {
        const int q0 = mtile * BM;
        const int r_lo = tid >> 4, c4 = tid & 15;
        #pragma unroll
        for (int it = 0; it < 8; ++it) {
            int r = r_lo + it * 8;
            cpasync16(sKu[1] + (r * KSTR + c4 * 4) * 4,
                      Qbase + (size_t)(q0 + r) * (HH * ED) + c4 * 4);
            cpasync16(sKu[0] + (r * KSTR + c4 * 4) * 4,
                      Kpbase + (size_t)r * ED + c4 * 4);
        }
        {   // V0: 64 e-rows x 128 B
            const int e_lo = tid >> 3, c8 = tid & 7;
            #pragma unroll
            for (int it = 0; it < 4; ++it) {
                int e = e_lo + it * 16;
                cpasync16(sVhu[0] + e * (VSH * 2) + c8 * 16,
                          Vtbase + (size_t)e * LQ + c8 * 8);
            }
        }
        if (tid < 16) cpasync16(sDu[0] + tid * 16, Dbase + tid * 4);
        cp_commit();
        cp_wait0();
    }
    __syncthreads();

    // ---- Q fragments from staging (raw layout), rna-rounded once ----
    uint32_t qa[8][4];
    {
        const float* qb = sK[1] + (wrow + g) * KSTR;
        #pragma unroll
        for (int k = 0; k < 8; ++k) {
            qa[k][0] = __float_as_uint(tf32r(qb[8 * k + t4]));
            qa[k][1] = __float_as_uint(tf32r(qb[8 * KSTR + 8 * k + t4]));
            qa[k][2] = __float_as_uint(tf32r(qb[8 * k + t4 + 4]));
            qa[k][3] = __float_as_uint(tf32r(qb[8 * KSTR + 8 * k + t4 + 4]));
        }
    }
    __syncthreads();   // all warps done reading sK1 before K(1) prefetch lands there

    float m_i[2] = {-1e30f, -1e30f};
    float l_i[2] = {0.f, 0.f};
    float Oacc[8][4];
    #pragma unroll
    for (int j = 0; j < 8; ++j)
        #pragma unroll
        for (int i = 0; i < 4; ++i) Oacc[j][i] = 0.f;

    const int row0 = mtile * BM + wrow + g;
    const int row1 = row0 + 8;

    for (int kt = 0; kt < nkt; ++kt) {
        cp_wait0();
        __syncthreads();   // tile kt data visible; buffers [1-cur] free for prefetch

        const int cur = kt & 1;

        // ---- prefetch tile kt+1 into the other buffers ----
        if (kt + 1 < nkt) {
            const int kr0 = (kt + 1) * BN;
            const int r_lo = tid >> 4, c4 = tid & 15;
            #pragma unroll
            for (int it = 0; it < 8; ++it) {
                int r = r_lo + it * 8;
                cpasync16(sKu[1 - cur] + (r * KSTR + c4 * 4) * 4,
                          Kpbase + (size_t)(kr0 + r) * ED + c4 * 4);
            }
            const int e_lo = tid >> 3, c8 = tid & 7;
            #pragma unroll
            for (int it = 0; it < 4; ++it) {
                int e = e_lo + it * 16;
                cpasync16(sVhu[1 - cur] + e * (VSH * 2) + c8 * 16,
                          Vtbase + (size_t)e * LQ + kr0 + c8 * 8);
            }
            if (tid < 16) cpasync16(sDu[1 - cur] + tid * 16, Dbase + kr0 + tid * 4);
            cp_commit();
        }

        // ---- S = Q @ K^T (tf32) ----
        float Sacc[8][4];
        #pragma unroll
        for (int j = 0; j < 8; ++j)
            #pragma unroll
            for (int i = 0; i < 4; ++i) Sacc[j][i] = 0.f;

        const float* sKc = sK[cur];
        #pragma unroll
        for (int k = 0; k < 8; ++k) {
            #pragma unroll
            for (int j = 0; j < 8; ++j) {
                float2 bb = *(const float2*)(sKc + (8 * j + g) * KSTR + 8 * k + 2 * t4);
                mma_tf32(Sacc[j], qa[k],
                         __float_as_uint(bb.x), __float_as_uint(bb.y));
            }
        }

        // ---- scale + delta + causal mask ----
        const float* sDc = sD[cur];
        const int cb = kt * BN + 2 * t4;
        #pragma unroll
        for (int j = 0; j < 8; ++j) {
            int c0 = cb + 8 * j;
            float2 d = *(const float2*)(sDc + 8 * j + 2 * t4);
            float dx = d.x * scale, dy = d.y * scale;
            float s0 = Sacc[j][0] * ts + dx;
            float s1 = Sacc[j][1] * ts + dy;
            float s2 = Sacc[j][2] * ts + dx;
            float s3 = Sacc[j][3] * ts + dy;
            if (c0     > row0) s0 = -1e30f;
            if (c0 + 1 > row0) s1 = -1e30f;
            if (c0     > row1) s2 = -1e30f;
            if (c0 + 1 > row1) s3 = -1e30f;
            Sacc[j][0] = s0; Sacc[j][1] = s1; Sacc[j][2] = s2; Sacc[j][3] = s3;
        }

        // ---- online softmax; P packed to half2 in registers ----
        uint32_t ph[8][2];   // [j][hh] = half2 {p(col 2t4), p(col 2t4+1)}
        #pragma unroll
        for (int hh = 0; hh < 2; ++hh) {
            float mx = -1e30f;
            #pragma unroll
            for (int j = 0; j < 8; ++j)
                mx = fmaxf(mx, fmaxf(Sacc[j][2 * hh], Sacc[j][2 * hh + 1]));
            mx = fmaxf(mx, __shfl_xor_sync(0xffffffffu, mx, 1));
            mx = fmaxf(mx, __shfl_xor_sync(0xffffffffu, mx, 2));
            float mnew  = fmaxf(m_i[hh], mx);
            float alpha = __expf(m_i[hh] - mnew);
            float psum = 0.f;
            #pragma unroll
            for (int j = 0; j < 8; ++j) {
                float p0 = __expf(Sacc[j][2 * hh]     - mnew);
                float p1 = __expf(Sacc[j][2 * hh + 1] - mnew);
                psum += p0 + p1;
                ph[j][hh] = pack_h2(p0, p1);
            }
            psum += __shfl_xor_sync(0xffffffffu, psum, 1);
            psum += __shfl_xor_sync(0xffffffffu, psum, 2);
            l_i[hh] = l_i[hh] * alpha + psum;
            m_i[hh] = mnew;
            #pragma unroll
            for (int j = 0; j < 8; ++j) {
                Oacc[j][2 * hh]     *= alpha;
                Oacc[j][2 * hh + 1] *= alpha;
            }
        }

        // ---- O += P @ V (fp16 m16n8k16; A = repacked S-fragments) ----
        const __half* sVc = sVh[cur];
        #pragma unroll
        for (int kk = 0; kk < 4; ++kk) {
            uint32_t A[4] = { ph[2 * kk][0], ph[2 * kk][1],
                              ph[2 * kk + 1][0], ph[2 * kk + 1][1] };
            #pragma unroll
            for (int j = 0; j < 8; ++j) {
                uint2 bv = *(const uint2*)(sVc + (8 * j + g) * VSH + 16 * kk + 4 * t4);
                mma_f16(Oacc[j], A, bv.x, bv.y);
            }
        }
    }

    // ---- finalize & write ----
    {
        float inv0 = 1.0f / l_i[0];
        float inv1 = 1.0f / l_i[1];
        float* o0 = Og + (((size_t)(b * LQ + row0)) * HH + h) * ED;
        float* o1 = Og + (((size_t)(b * LQ + row1)) * HH + h) * ED;
        #pragma unroll
        for (int j = 0; j < 8; ++j) {
            int e = 8 * j + 2 * t4;
            *(float2*)(o0 + e) = make_float2(Oacc[j][0] * inv0, Oacc[j][1] * inv0);
            *(float2*)(o1 + e) = make_float2(Oacc[j][2] * inv1, Oacc[j][3] * inv1);
        }
    }
}

extern "C" void kernel_launch(void* const* d_in, const int* in_sizes, int n_in,
                              void* d_out, int out_size)
{
    const float* Q     = (const float*)d_in[0];
    const float* K     = (const float*)d_in[1];
    const float* V     = (const float*)d_in[2];
    const float* tau   = (const float*)d_in[3];
    const float* delta = (const float*)d_in[4];
    float* out = (float*)d_out;

    cudaFuncSetAttribute(dsattn_tc,
                         cudaFuncAttributeMaxDynamicSharedMemorySize, SMEM_BYTES);

    dim3 pgrid(LQ / 64, HH, 2);
    prep_kernel<<<pgrid, 256>>>(K, V);

    dim3 grid(LQ / BM, HH, 2);   // 512 CTAs, single wave at 4 CTAs/SM
    dsattn_tc<<<grid, NTHREADS, SMEM_BYTES>>>(Q, tau, delta, out);
}

// round 14
// speedup vs baseline: 1.2096x; 1.2096x over previous
#include <cuda_runtime.h>
#include <cuda_fp16.h>
#include <cstdint>

// DSAttention flash attention: QK in tf32 mma.m16n8k8, PV in fp16 mma.m16n8k16
// with the S->A fragment identity (P never touches smem). Full double-buffered
// cp.async (K, V, delta), ONE barrier per tile. 3 CTAs/SM (no reg cap -> no spill).
// Prep kernel: K rna->tf32 interleaved (c,c+4); V -> fp16 transposed [e][s]
// with 16-group interleave -> one LDS.64 per B-frag.

#define LQ 2048
#define HH 8
#define BM 64
#define BN 64
#define ED 64
#define NTHREADS 128
#define KSTR 72            // floats; 72%32==8 -> 2-way max on frag LDS.64
#define VSH 72             // halves per e-row (144 B)

#define SK_F   (64 * KSTR)             // 4608 floats per K buffer
#define SVH_B  (64 * VSH * 2)          // 9216 bytes per V buffer
#define OFF_K0 0
#define OFF_K1 (SK_F)
#define OFF_VH (2 * SK_F)
#define OFF_D  (OFF_VH + (2 * SVH_B) / 4)
#define SMEM_FLOATS (OFF_D + 128 + 16)
#define SMEM_BYTES  (SMEM_FLOATS * 4)  // ~55.9 KB

__device__ float  g_Kp[2 * 8 * 2048 * 64];    // 8 MB: tf32-rounded, interleaved
__device__ __half g_Vth[2 * 8 * 64 * 2048];   // 4 MB: fp16, [bh][e][s] interleaved

__device__ __forceinline__ float tf32r(float x) {
    uint32_t u;
    asm("cvt.rna.tf32.f32 %0, %1;" : "=r"(u) : "f"(x));
    return __uint_as_float(u);
}
__device__ __forceinline__ uint32_t pack_h2(float a, float b) {
    __half2 h = __floats2half2_rn(a, b);
    return *(uint32_t*)&h;
}
__device__ __forceinline__ void cpasync16(uint32_t dst, const void* src) {
    asm volatile("cp.async.cg.shared.global [%0], [%1], 16;" :: "r"(dst), "l"(src));
}
__device__ __forceinline__ void cp_commit() {
    asm volatile("cp.async.commit_group;" ::: "memory");
}
__device__ __forceinline__ void cp_wait0() {
    asm volatile("cp.async.wait_group 0;" ::: "memory");
}

__device__ __forceinline__ void mma_tf32(float* d, const uint32_t* a,
                                         uint32_t b0, uint32_t b1) {
    asm volatile(
        "mma.sync.aligned.m16n8k8.row.col.f32.tf32.tf32.f32 "
        "{%0,%1,%2,%3}, {%4,%5,%6,%7}, {%8,%9}, {%0,%1,%2,%3};"
        : "+f"(d[0]), "+f"(d[1]), "+f"(d[2]), "+f"(d[3])
        : "r"(a[0]), "r"(a[1]), "r"(a[2]), "r"(a[3]), "r"(b0), "r"(b1));
}
__device__ __forceinline__ void mma_f16(float* d, const uint32_t* a,
                                        uint32_t b0, uint32_t b1) {
    asm volatile(
        "mma.sync.aligned.m16n8k16.row.col.f32.f16.f16.f32 "
        "{%0,%1,%2,%3}, {%4,%5,%6,%7}, {%8,%9}, {%0,%1,%2,%3};"
        : "+f"(d[0]), "+f"(d[1]), "+f"(d[2]), "+f"(d[3])
        : "r"(a[0]), "r"(a[1]), "r"(a[2]), "r"(a[3]), "r"(b0), "r"(b1));
}

// ---------------- prep ----------------
__global__ __launch_bounds__(256)
void prep_kernel(const float* __restrict__ Kg, const float* __restrict__ Vg)
{
    const int stile = blockIdx.x;
    const int h     = blockIdx.y;
    const int b     = blockIdx.z;
    const int tid   = threadIdx.x;
    const int bh    = b * HH + h;
    const int s0    = stile * 64;

    __shared__ float tile[64][65];

    const float* Kbh = Kg + ((size_t)(b * LQ) * HH + h) * ED;
    float* Kp = g_Kp + (size_t)bh * LQ * ED;
    #pragma unroll
    for (int it = 0; it < 2; ++it) {
        int u  = tid + it * 256;
        int r  = u >> 3;
        int c8 = u & 7;
        const float* src = Kbh + (size_t)(s0 + r) * (HH * ED) + 8 * c8;
        float4 a  = *(const float4*)(src);
        float4 bb = *(const float4*)(src + 4);
        a.x = tf32r(a.x); a.y = tf32r(a.y); a.z = tf32r(a.z); a.w = tf32r(a.w);
        bb.x = tf32r(bb.x); bb.y = tf32r(bb.y); bb.z = tf32r(bb.z); bb.w = tf32r(bb.w);
        float* dst = Kp + (size_t)(s0 + r) * ED + 8 * c8;
        *(float4*)(dst)     = make_float4(a.x, bb.x, a.y, bb.y);
        *(float4*)(dst + 4) = make_float4(a.z, bb.z, a.w, bb.w);
    }

    const float* Vbh = Vg + ((size_t)(b * LQ) * HH + h) * ED;
    #pragma unroll
    for (int it = 0; it < 4; ++it) {
        int u  = tid + it * 256;
        int r  = u >> 4;
        int c4 = u & 15;
        float4 v = *(const float4*)(Vbh + (size_t)(s0 + r) * (HH * ED) + 4 * c4);
        tile[r][4 * c4 + 0] = v.x;
        tile[r][4 * c4 + 1] = v.y;
        tile[r][4 * c4 + 2] = v.z;
        tile[r][4 * c4 + 3] = v.w;
    }
    __syncthreads();
    // Physical p within 16-group holds logical s = 2*(p>>2) + (p&1) + 8*((p>>1)&1)
    {
        int e   = tid >> 2;
        int grp = tid & 3;
        __half hh16[16];
        #pragma unroll
        for (int p = 0; p < 16; ++p) {
            int s_l = grp * 16 + 2 * (p >> 2) + (p & 1) + 8 * ((p >> 1) & 1);
            hh16[p] = __float2half_rn(tile[s_l][e]);
        }
        __half* dst = g_Vth + ((size_t)bh * ED + e) * LQ + s0 + grp * 16;
        *(uint4*)(dst)     = *(uint4*)(hh16);
        *(uint4*)(dst + 8) = *(uint4*)(hh16 + 8);
    }
}

// ---------------- main ----------------
__global__ __launch_bounds__(NTHREADS, 3)
void dsattn_tc(const float* __restrict__ Qg, const float* __restrict__ Taug,
               const float* __restrict__ Dg, float* __restrict__ Og)
{
    const float scale = 0.125f;

    const int mtile = (int)gridDim.x - 1 - (int)blockIdx.x;
    const int h     = blockIdx.y;
    const int b     = blockIdx.z;
    const int bh    = b * HH + h;

    const int tid  = threadIdx.x;
    const int wid  = tid >> 5;
    const int lane = tid & 31;
    const int g    = lane >> 2;
    const int t4   = lane & 3;

    extern __shared__ float smem[];
    float*  sK[2];
    sK[0] = smem + OFF_K0;
    sK[1] = smem + OFF_K1;
    __half* sVh[2];
    sVh[0] = (__half*)(smem + OFF_VH);
    sVh[1] = sVh[0] + 64 * VSH;
    float* sD[2];
    sD[0] = smem + OFF_D;
    sD[1] = sD[0] + 64;

    const uint32_t su   = (uint32_t)__cvta_generic_to_shared(smem);
    const uint32_t sKu[2]  = { su + OFF_K0 * 4, su + OFF_K1 * 4 };
    const uint32_t sVhu[2] = { su + OFF_VH * 4, su + OFF_VH * 4 + SVH_B };
    const uint32_t sDu[2]  = { su + OFF_D * 4,  su + OFF_D * 4 + 256 };

    const float ts = Taug[b] * scale;
    const int wrow = wid * 16;

    const float*  Qbase  = Qg + ((size_t)(b * LQ) * HH + h) * ED;
    const float*  Kpbase = g_Kp + (size_t)bh * LQ * ED;
    const __half* Vtbase = g_Vth + (size_t)bh * ED * LQ;
    const float*  Dbase  = Dg + b * LQ;

    const int nkt = mtile + 1;

    // ---- prologue: Q -> sK1 (staging), K0, V0, D0 ----
    {
        const int q0 = mtile * BM;
        const int r_lo = tid >> 4, c4 = tid & 15;
        #pragma unroll
        for (int it = 0; it < 8; ++it) {
            int r = r_lo + it * 8;
            cpasync16(sKu[1] + (r * KSTR + c4 * 4) * 4,
                      Qbase + (size_t)(q0 + r) * (HH * ED) + c4 * 4);
            cpasync16(sKu[0] + (r * KSTR + c4 * 4) * 4,
                      Kpbase + (size_t)r * ED + c4 * 4);
        }
        {
            const int e_lo = tid >> 3, c8 = tid & 7;
            #pragma unroll
            for (int it = 0; it < 4; ++it) {
                int e = e_lo + it * 16;
                cpasync16(sVhu[0] + e * (VSH * 2) + c8 * 16,
                          Vtbase + (size_t)e * LQ + c8 * 8);
            }
        }
        if (tid < 16) cpasync16(sDu[0] + tid * 16, Dbase + tid * 4);
        cp_commit();
        cp_wait0();
    }
    __syncthreads();

    // ---- Q fragments from staging (raw layout), rna-rounded once ----
    uint32_t qa[8][4];
    {
        const float* qb = sK[1] + (wrow + g) * KSTR;
        #pragma unroll
        for (int k = 0; k < 8; ++k) {
            qa[k][0] = __float_as_uint(tf32r(qb[8 * k + t4]));
            qa[k][1] = __float_as_uint(tf32r(qb[8 * KSTR + 8 * k + t4]));
            qa[k][2] = __float_as_uint(tf32r(qb[8 * k + t4 + 4]));
            qa[k][3] = __float_as_uint(tf32r(qb[8 * KSTR + 8 * k + t4 + 4]));
        }
    }
    __syncthreads();   // all warps done reading sK1 before K(1) prefetch lands there

    float m_i[2] = {-1e30f, -1e30f};
    float l_i[2] = {0.f, 0.f};
    float Oacc[8][4];
    #pragma unroll
    for (int j = 0; j < 8; ++j)
        #pragma unroll
        for (int i = 0; i < 4; ++i) Oacc[j][i] = 0.f;

    const int row0 = mtile * BM + wrow + g;
    const int row1 = row0 + 8;

    for (int kt = 0; kt < nkt; ++kt) {
        cp_wait0();
        __syncthreads();   // tile kt data visible; buffers [1-cur] free

        const int cur = kt & 1;

        // ---- prefetch tile kt+1 ----
        if (kt + 1 < nkt) {
            const int kr0 = (kt + 1) * BN;
            const int r_lo = tid >> 4, c4 = tid & 15;
            #pragma unroll
            for (int it = 0; it < 8; ++it) {
                int r = r_lo + it * 8;
                cpasync16(sKu[1 - cur] + (r * KSTR + c4 * 4) * 4,
                          Kpbase + (size_t)(kr0 + r) * ED + c4 * 4);
            }
            const int e_lo = tid >> 3, c8 = tid & 7;
            #pragma unroll
            for (int it = 0; it < 4; ++it) {
                int e = e_lo + it * 16;
                cpasync16(sVhu[1 - cur] + e * (VSH * 2) + c8 * 16,
                          Vtbase + (size_t)e * LQ + kr0 + c8 * 8);
            }
            if (tid < 16) cpasync16(sDu[1 - cur] + tid * 16, Dbase + kr0 + tid * 4);
            cp_commit();
        }

        // ---- S = Q @ K^T (tf32) ----
        float Sacc[8][4];
        #pragma unroll
        for (int j = 0; j < 8; ++j)
            #pragma unroll
            for (int i = 0; i < 4; ++i) Sacc[j][i] = 0.f;

        const float* sKc = sK[cur];
        #pragma unroll
        for (int k = 0; k < 8; ++k) {
            #pragma unroll
            for (int j = 0; j < 8; ++j) {
                float2 bb = *(const float2*)(sKc + (8 * j + g) * KSTR + 8 * k + 2 * t4);
                mma_tf32(Sacc[j], qa[k],
                         __float_as_uint(bb.x), __float_as_uint(bb.y));
            }
        }

        // ---- scale + delta + causal mask ----
        const float* sDc = sD[cur];
        const int cb = kt * BN + 2 * t4;
        #pragma unroll
        for (int j = 0; j < 8; ++j) {
            int c0 = cb + 8 * j;
            float2 d = *(const float2*)(sDc + 8 * j + 2 * t4);
            float dx = d.x * scale, dy = d.y * scale;
            float s0 = Sacc[j][0] * ts + dx;
            float s1 = Sacc[j][1] * ts + dy;
            float s2 = Sacc[j][2] * ts + dx;
            float s3 = Sacc[j][3] * ts + dy;
            if (c0     > row0) s0 = -1e30f;
            if (c0 + 1 > row0) s1 = -1e30f;
            if (c0     > row1) s2 = -1e30f;
            if (c0 + 1 > row1) s3 = -1e30f;
            Sacc[j][0] = s0; Sacc[j][1] = s1; Sacc[j][2] = s2; Sacc[j][3] = s3;
        }

        // ---- online softmax; P packed to half2 in registers ----
        uint32_t ph[8][2];
        #pragma unroll
        for (int hh = 0; hh < 2; ++hh) {
            float mx = -1e30f;
            #pragma unroll
            for (int j = 0; j < 8; ++j)
                mx = fmaxf(mx, fmaxf(Sacc[j][2 * hh], Sacc[j][2 * hh + 1]));
            mx = fmaxf(mx, __shfl_xor_sync(0xffffffffu, mx, 1));
            mx = fmaxf(mx, __shfl_xor_sync(0xffffffffu, mx, 2));
            float mnew  = fmaxf(m_i[hh], mx);
            float alpha = __expf(m_i[hh] - mnew);
            float psum = 0.f;
            #pragma unroll
            for (int j = 0; j < 8; ++j) {
                float p0 = __expf(Sacc[j][2 * hh]     - mnew);
                float p1 = __expf(Sacc[j][2 * hh + 1] - mnew);
                psum += p0 + p1;
                ph[j][hh] = pack_h2(p0, p1);
            }
            psum += __shfl_xor_sync(0xffffffffu, psum, 1);
            psum += __shfl_xor_sync(0xffffffffu, psum, 2);
            l_i[hh] = l_i[hh] * alpha + psum;
            m_i[hh] = mnew;
            #pragma unroll
            for (int j = 0; j < 8; ++j) {
                Oacc[j][2 * hh]     *= alpha;
                Oacc[j][2 * hh + 1] *= alpha;
            }
        }

        // ---- O += P @ V (fp16 m16n8k16; A = repacked S-fragments) ----
        const __half* sVc = sVh[cur];
        #pragma unroll
        for (int kk = 0; kk < 4; ++kk) {
            uint32_t A[4] = { ph[2 * kk][0], ph[2 * kk][1],
                              ph[2 * kk + 1][0], ph[2 * kk + 1][1] };
            #pragma unroll
            for (int j = 0; j < 8; ++j) {
                uint2 bv = *(const uint2*)(sVc + (8 * j + g) * VSH + 16 * kk + 4 * t4);
                mma_f16(Oacc[j], A, bv.x, bv.y);
            }
        }
    }

    // ---- finalize & write ----
    {
        float inv0 = 1.0f / l_i[0];
        float inv1 = 1.0f / l_i[1];
        float* o0 = Og + (((size_t)(b * LQ + row0)) * HH + h) * ED;
        float* o1 = Og + (((size_t)(b * LQ + row1)) * HH + h) * ED;
        #pragma unroll
        for (int j = 0; j < 8; ++j) {
            int e = 8 * j + 2 * t4;
            *(float2*)(o0 + e) = make_float2(Oacc[j][0] * inv0, Oacc[j][1] * inv0);
            *(float2*)(o1 + e) = make_float2(Oacc[j][2] * inv1, Oacc[j][3] * inv1);
        }
    }
}

extern "C" void kernel_launch(void* const* d_in, const int* in_sizes, int n_in,
                              void* d_out, int out_size)
{
    const float* Q     = (const float*)d_in[0];
    const float* K     = (const float*)d_in[1];
    const float* V     = (const float*)d_in[2];
    const float* tau   = (const float*)d_in[3];
    const float* delta = (const float*)d_in[4];
    float* out = (float*)d_out;

    cudaFuncSetAttribute(dsattn_tc,
                         cudaFuncAttributeMaxDynamicSharedMemorySize, SMEM_BYTES);

    dim3 pgrid(LQ / 64, HH, 2);
    prep_kernel<<<pgrid, 256>>>(K, V);

    dim3 grid(LQ / BM, HH, 2);   // 512 CTAs
    dsattn_tc<<<grid, NTHREADS, SMEM_BYTES>>>(Q, tau, delta, out);
}

// round 15
// speedup vs baseline: 1.3013x; 1.0759x over previous
#include <cuda_runtime.h>
#include <cuda_fp16.h>
#include <cstdint>

// DSAttention flash attention, all-fp16 tensor-core path (fp32 accumulate):
// QK and PV both mma.m16n8k16.f16 with S->A fragment identity (P in registers).
// Prep: K -> fp16 [bh][s][e] with 16-group e-interleave; V -> fp16 [bh][e][s]
// transposed with 16-group s-interleave. One LDS.64 per B-fragment.
// Double-buffered cp.async (K,V,delta), one barrier per tile, 3 CTAs/SM.

#define LQ 2048
#define HH 8
#define BM 64
#define BN 64
#define ED 64
#define NTHREADS 128
#define KVSH 72                  // halves per row (144 B)
#define KVB  (64 * KVSH * 2)     // 9216 B per tile buffer
#define QSTR 68                  // floats per Q-stage row

#define OFFB_K0 0
#define OFFB_K1 (KVB)
#define OFFB_V0 (2 * KVB)
#define OFFB_V1 (3 * KVB)
#define OFFB_D0 (4 * KVB)
#define OFFB_D1 (4 * KVB + 256)
#define OFFB_Q  (4 * KVB + 512)
#define SMEM_BYTES (OFFB_Q + 64 * QSTR * 4)   // 54784 B

__device__ __half g_Kh[2 * 8 * 2048 * 64];    // 4 MB: fp16 K, e-interleaved
__device__ __half g_Vth[2 * 8 * 64 * 2048];   // 4 MB: fp16 V, [bh][e][s] interleaved

__device__ __forceinline__ uint32_t pack_h2(float a, float b) {
    __half2 h = __floats2half2_rn(a, b);
    return *(uint32_t*)&h;
}
__device__ __forceinline__ void cpasync16(uint32_t dst, const void* src) {
    asm volatile("cp.async.cg.shared.global [%0], [%1], 16;" :: "r"(dst), "l"(src));
}
__device__ __forceinline__ void cp_commit() {
    asm volatile("cp.async.commit_group;" ::: "memory");
}
__device__ __forceinline__ void cp_wait0() {
    asm volatile("cp.async.wait_group 0;" ::: "memory");
}
__device__ __forceinline__ void mma_f16(float* d, const uint32_t* a,
                                        uint32_t b0, uint32_t b1) {
    asm volatile(
        "mma.sync.aligned.m16n8k16.row.col.f32.f16.f16.f32 "
        "{%0,%1,%2,%3}, {%4,%5,%6,%7}, {%8,%9}, {%0,%1,%2,%3};"
        : "+f"(d[0]), "+f"(d[1]), "+f"(d[2]), "+f"(d[3])
        : "r"(a[0]), "r"(a[1]), "r"(a[2]), "r"(a[3]), "r"(b0), "r"(b1));
}

// perm within a 16-group: physical p holds logical 2*(p>>2) + (p&1) + 8*((p>>1)&1)
__device__ __forceinline__ int perm16(int p) {
    return 2 * (p >> 2) + (p & 1) + 8 * ((p >> 1) & 1);
}

// ---------------- prep ----------------
__global__ __launch_bounds__(256)
void prep_kernel(const float* __restrict__ Kg, const float* __restrict__ Vg)
{
    const int stile = blockIdx.x;
    const int h     = blockIdx.y;
    const int b     = blockIdx.z;
    const int tid   = threadIdx.x;
    const int bh    = b * HH + h;
    const int s0    = stile * 64;

    __shared__ float tile[64][65];

    // ---- K: fp16, same [s][e] order, e-interleave per 16-group ----
    {
        int r   = tid >> 2;          // 0..63
        int grp = tid & 3;           // 0..3
        const float* src = Kg + ((size_t)(b * LQ + s0 + r) * HH + h) * ED + grp * 16;
        float f[16];
        *(float4*)(f)      = *(const float4*)(src);
        *(float4*)(f + 4)  = *(const float4*)(src + 4);
        *(float4*)(f + 8)  = *(const float4*)(src + 8);
        *(float4*)(f + 12) = *(const float4*)(src + 12);
        __half hh16[16];
        #pragma unroll
        for (int p = 0; p < 16; ++p) hh16[p] = __float2half_rn(f[perm16(p)]);
        __half* dst = g_Kh + ((size_t)bh * LQ + s0 + r) * ED + grp * 16;
        *(uint4*)(dst)     = *(uint4*)(hh16);
        *(uint4*)(dst + 8) = *(uint4*)(hh16 + 8);
    }

    // ---- V: fp16, transpose to [e][s], s-interleave per 16-group ----
    const float* Vbh = Vg + ((size_t)(b * LQ) * HH + h) * ED;
    #pragma unroll
    for (int it = 0; it < 4; ++it) {
        int u  = tid + it * 256;
        int r  = u >> 4;
        int c4 = u & 15;
        float4 v = *(const float4*)(Vbh + (size_t)(s0 + r) * (HH * ED) + 4 * c4);
        tile[r][4 * c4 + 0] = v.x;
        tile[r][4 * c4 + 1] = v.y;
        tile[r][4 * c4 + 2] = v.z;
        tile[r][4 * c4 + 3] = v.w;
    }
    __syncthreads();
    {
        int e   = tid >> 2;
        int grp = tid & 3;
        __half hh16[16];
        #pragma unroll
        for (int p = 0; p < 16; ++p)
            hh16[p] = __float2half_rn(tile[grp * 16 + perm16(p)][e]);
        __half* dst = g_Vth + ((size_t)bh * ED + e) * LQ + s0 + grp * 16;
        *(uint4*)(dst)     = *(uint4*)(hh16);
        *(uint4*)(dst + 8) = *(uint4*)(hh16 + 8);
    }
}

// ---------------- main ----------------
__global__ __launch_bounds__(NTHREADS, 3)
void dsattn_tc(const float* __restrict__ Qg, const float* __restrict__ Taug,
               const float* __restrict__ Dg, float* __restrict__ Og)
{
    const float scale = 0.125f;

    const int mtile = (int)gridDim.x - 1 - (int)blockIdx.x;   // heavy first
    const int h     = blockIdx.y;
    const int b     = blockIdx.z;
    const int bh    = b * HH + h;

    const int tid  = threadIdx.x;
    const int wid  = tid >> 5;
    const int lane = tid & 31;
    const int g    = lane >> 2;
    const int t4   = lane & 3;

    extern __shared__ char smemc[];
    __half* sKh[2] = { (__half*)(smemc + OFFB_K0), (__half*)(smemc + OFFB_K1) };
    __half* sVh[2] = { (__half*)(smemc + OFFB_V0), (__half*)(smemc + OFFB_V1) };
    float*  sD [2] = { (float*)(smemc + OFFB_D0),  (float*)(smemc + OFFB_D1) };
    float*  sQ     = (float*)(smemc + OFFB_Q);

    const uint32_t su = (uint32_t)__cvta_generic_to_shared(smemc);
    const uint32_t sKu[2] = { su + OFFB_K0, su + OFFB_K1 };
    const uint32_t sVu[2] = { su + OFFB_V0, su + OFFB_V1 };
    const uint32_t sDu[2] = { su + OFFB_D0, su + OFFB_D1 };
    const uint32_t sQu    = su + OFFB_Q;

    const float ts = Taug[b] * scale;
    const int wrow = wid * 16;

    const float*  Qbase  = Qg + ((size_t)(b * LQ) * HH + h) * ED;
    const __half* Khbase = g_Kh + (size_t)bh * LQ * ED;
    const __half* Vtbase = g_Vth + (size_t)bh * ED * LQ;
    const float*  Dbase  = Dg + b * LQ;

    const int nkt = mtile + 1;
    const int rlo8 = tid >> 3, c8 = tid & 7;   // KV loader coords (128 B rows)

    // ---- prologue: Q stage + K0 + V0 + D0, one wait ----
    {
        const int q0 = mtile * BM;
        const int r_lo = tid >> 4, c4 = tid & 15;
        #pragma unroll
        for (int it = 0; it < 8; ++it) {
            int r = r_lo + it * 8;
            cpasync16(sQu + (r * QSTR + c4 * 4) * 4,
                      Qbase + (size_t)(q0 + r) * (HH * ED) + c4 * 4);
        }
        #pragma unroll
        for (int it = 0; it < 4; ++it) {
            int r = rlo8 + it * 16;
            cpasync16(sKu[0] + r * (KVSH * 2) + c8 * 16,
                      Khbase + (size_t)r * ED + c8 * 8);
            cpasync16(sVu[0] + r * (KVSH * 2) + c8 * 16,
                      Vtbase + (size_t)r * LQ + c8 * 8);
        }
        if (tid < 16) cpasync16(sDu[0] + tid * 16, Dbase + tid * 4);
        cp_commit();
        cp_wait0();
    }
    __syncthreads();

    // ---- Q fragments as half2 (one-time) ----
    uint32_t qh[4][4];
    {
        const float* qb = sQ + (wrow + g) * QSTR;
        #pragma unroll
        for (int kk = 0; kk < 4; ++kk) {
            float2 x0 = *(const float2*)(qb + 16 * kk + 2 * t4);
            float2 x1 = *(const float2*)(qb + 8 * QSTR + 16 * kk + 2 * t4);
            float2 x2 = *(const float2*)(qb + 16 * kk + 8 + 2 * t4);
            float2 x3 = *(const float2*)(qb + 8 * QSTR + 16 * kk + 8 + 2 * t4);
            qh[kk][0] = pack_h2(x0.x, x0.y);
            qh[kk][1] = pack_h2(x1.x, x1.y);
            qh[kk][2] = pack_h2(x2.x, x2.y);
            qh[kk][3] = pack_h2(x3.x, x3.y);
        }
    }

    float m_i[2] = {-1e30f, -1e30f};
    float l_i[2] = {0.f, 0.f};
    float Oacc[8][4];
    #pragma unroll
    for (int j = 0; j < 8; ++j)
        #pragma unroll
        for (int i = 0; i < 4; ++i) Oacc[j][i] = 0.f;

    const int row0 = mtile * BM + wrow + g;
    const int row1 = row0 + 8;

    for (int kt = 0; kt < nkt; ++kt) {
        cp_wait0();
        __syncthreads();   // tile kt visible; buffers [1-cur] free

        const int cur = kt & 1;

        // ---- prefetch tile kt+1 ----
        if (kt + 1 < nkt) {
            const int kr0 = (kt + 1) * BN;
            #pragma unroll
            for (int it = 0; it < 4; ++it) {
                int r = rlo8 + it * 16;
                cpasync16(sKu[1 - cur] + r * (KVSH * 2) + c8 * 16,
                          Khbase + (size_t)(kr0 + r) * ED + c8 * 8);
                cpasync16(sVu[1 - cur] + r * (KVSH * 2) + c8 * 16,
                          Vtbase + (size_t)r * LQ + kr0 + c8 * 8);
            }
            if (tid < 16) cpasync16(sDu[1 - cur] + tid * 16, Dbase + kr0 + tid * 4);
            cp_commit();
        }

        // ---- S = Q @ K^T (fp16 m16n8k16) ----
        float Sacc[8][4];
        #pragma unroll
        for (int j = 0; j < 8; ++j)
            #pragma unroll
            for (int i = 0; i < 4; ++i) Sacc[j][i] = 0.f;

        const __half* sKc = sKh[cur];
        #pragma unroll
        for (int kk = 0; kk < 4; ++kk) {
            #pragma unroll
            for (int j = 0; j < 8; ++j) {
                uint2 bv = *(const uint2*)(sKc + (8 * j + g) * KVSH + 16 * kk + 4 * t4);
                mma_f16(Sacc[j], qh[kk], bv.x, bv.y);
            }
        }

        // ---- scale + delta + causal mask ----
        const float* sDc = sD[cur];
        const int cb = kt * BN + 2 * t4;
        #pragma unroll
        for (int j = 0; j < 8; ++j) {
            int c0 = cb + 8 * j;
            float2 d = *(const float2*)(sDc + 8 * j + 2 * t4);
            float dx = d.x * scale, dy = d.y * scale;
            float s0 = Sacc[j][0] * ts + dx;
            float s1 = Sacc[j][1] * ts + dy;
            float s2 = Sacc[j][2] * ts + dx;
            float s3 = Sacc[j][3] * ts + dy;
            if (c0     > row0) s0 = -1e30f;
            if (c0 + 1 > row0) s1 = -1e30f;
            if (c0     > row1) s2 = -1e30f;
            if (c0 + 1 > row1) s3 = -1e30f;
            Sacc[j][0] = s0; Sacc[j][1] = s1; Sacc[j][2] = s2; Sacc[j][3] = s3;
        }

        // ---- online softmax; P packed to half2 in registers ----
        uint32_t ph[8][2];
        #pragma unroll
        for (int hh = 0; hh < 2; ++hh) {
            float mx = -1e30f;
            #pragma unroll
            for (int j = 0; j < 8; ++j)
                mx = fmaxf(mx, fmaxf(Sacc[j][2 * hh], Sacc[j][2 * hh + 1]));
            mx = fmaxf(mx, __shfl_xor_sync(0xffffffffu, mx, 1));
            mx = fmaxf(mx, __shfl_xor_sync(0xffffffffu, mx, 2));
            float mnew  = fmaxf(m_i[hh], mx);
            float alpha = __expf(m_i[hh] - mnew);
            float psum = 0.f;
            #pragma unroll
            for (int j = 0; j < 8; ++j) {
                float p0 = __expf(Sacc[j][2 * hh]     - mnew);
                float p1 = __expf(Sacc[j][2 * hh + 1] - mnew);
                psum += p0 + p1;
                ph[j][hh] = pack_h2(p0, p1);
            }
            psum += __shfl_xor_sync(0xffffffffu, psum, 1);
            psum += __shfl_xor_sync(0xffffffffu, psum, 2);
            l_i[hh] = l_i[hh] * alpha + psum;
            m_i[hh] = mnew;
            #pragma unroll
            for (int j = 0; j < 8; ++j) {
                Oacc[j][2 * hh]     *= alpha;
                Oacc[j][2 * hh + 1] *= alpha;
            }
        }

        // ---- O += P @ V (fp16 m16n8k16; A = repacked S-fragments) ----
        const __half* sVc = sVh[cur];
        #pragma unroll
        for (int kk = 0; kk < 4; ++kk) {
            uint32_t A[4] = { ph[2 * kk][0], ph[2 * kk][1],
                              ph[2 * kk + 1][0], ph[2 * kk + 1][1] };
            #pragma unroll
            for (int j = 0; j < 8; ++j) {
                uint2 bv = *(const uint2*)(sVc + (8 * j + g) * KVSH + 16 * kk + 4 * t4);
                mma_f16(Oacc[j], A, bv.x, bv.y);
            }
        }
    }

    // ---- finalize & write ----
    {
        float inv0 = 1.0f / l_i[0];
        float inv1 = 1.0f / l_i[1];
        float* o0 = Og + (((size_t)(b * LQ + row0)) * HH + h) * ED;
        float* o1 = Og + (((size_t)(b * LQ + row1)) * HH + h) * ED;
        #pragma unroll
        for (int j = 0; j < 8; ++j) {
            int e = 8 * j + 2 * t4;
            *(float2*)(o0 + e) = make_float2(Oacc[j][0] * inv0, Oacc[j][1] * inv0);
            *(float2*)(o1 + e) = make_float2(Oacc[j][2] * inv1, Oacc[j][3] * inv1);
        }
    }
}

extern "C" void kernel_launch(void* const* d_in, const int* in_sizes, int n_in,
                              void* d_out, int out_size)
{
    const float* Q     = (const float*)d_in[0];
    const float* K     = (const float*)d_in[1];
    const float* V     = (const float*)d_in[2];
    const float* tau   = (const float*)d_in[3];
    const float* delta = (const float*)d_in[4];
    float* out = (float*)d_out;

    cudaFuncSetAttribute(dsattn_tc,
                         cudaFuncAttributeMaxDynamicSharedMemorySize, SMEM_BYTES);

    dim3 pgrid(LQ / 64, HH, 2);
    prep_kernel<<<pgrid, 256>>>(K, V);

    dim3 grid(LQ / BM, HH, 2);   // 512 CTAs
    dsattn_tc<<<grid, NTHREADS, SMEM_BYTES>>>(Q, tau, delta, out);
}